// round 16
// baseline (speedup 1.0000x reference)
#include <cuda_runtime.h>
#include <cstdint>

// Problem constants
#define NPTS   32768            // 32 * 32 * 32 points
#define DIM    64               // embedding dim
#define NE     1024             // codebook size
#define HW     1024             // 32*32 spatial
#define BHW    65536            // 64 channels * 1024 hw (per-batch stride in z)
#define PTSB   64               // points per tile
#define CCH    128              // codes per CTA
#define EPITCH 129              // es row pitch (floats) — kills STS transpose conflicts
#define NTILE  (NPTS / PTSB)    // 512 point tiles
#define NSPLIT 8                // code-split CTAs per tile
#define NBLK   (NTILE * NSPLIT) // 4096 CTAs

// Output layout (flat concat of reference return tuple, float32):
// loss[1], z_q[2097152], perplexity[1], min_encodings[33554432], indices[32768]
#define OFF_LOSS 0ULL
#define OFF_ZQ   1ULL
#define OFF_PERP 2097153ULL
#define OFF_ENC  2097154ULL
#define OFF_IDX  35651586ULL

// Self-cleaning state: zero-init is the "ready" state; consumers reset after use.
// Argmin keys are MAX-keys: key = (~ordf(d) << 32) | (1023 - code); 0 == worst.
__device__ unsigned long long d_best[NPTS];   // zero-init; epilogue resets
__device__ unsigned int       d_tile[NTILE];  // zero-init; epilogue resets
__device__ unsigned int       d_count[NE];    // zero-init; finalize resets
__device__ float              d_loss;         // zero-init; finalize resets
__device__ unsigned int       d_done;         // zero-init; finalize resets

// ---------------------------------------------------------------- helpers
struct __align__(16) ull2 { unsigned long long a, b; };

static __device__ __forceinline__ unsigned long long pk2(float v) {
    unsigned long long r;
    asm("mov.b64 %0, {%1,%2};" : "=l"(r) : "f"(v), "f"(v));
    return r;
}
static __device__ __forceinline__ void ffma2(unsigned long long& d,
                                             unsigned long long a,
                                             unsigned long long b) {
    asm("fma.rn.f32x2 %0, %1, %2, %0;" : "+l"(d) : "l"(a), "l"(b));
}
static __device__ __forceinline__ float2 upk(unsigned long long v) {
    float2 f;
    asm("mov.b64 {%0,%1}, %2;" : "=f"(f.x), "=f"(f.y) : "l"(v));
    return f;
}
static __device__ __forceinline__ unsigned int ordf(float x) {
    unsigned int b = __float_as_uint(x);
    return b ^ (unsigned int)(((int)b >> 31) | 0x80000000);
}

// ---------------------------------------------------------------- the single kernel
// CTA = (tile, octant): 64 points x 128 codes.
// 128 threads = 8 pt-groups (pt_t, 8 pts) x 16 code-groups (cg, 8 codes)
// thread tile: 8 points (4 NATURAL f32x2 pairs) x 8 codes (pk2-dup es) — R15 loop.
__global__ void __launch_bounds__(128, 4)
vq_main_kernel(const float* __restrict__ z, const float* __restrict__ emb,
               float* __restrict__ out)
{
    __shared__ __align__(16) float zs[DIM][PTSB];      // [k][pt] 16 KB
    __shared__ __align__(16) float es[DIM][EPITCH];    // [k][c] transposed, 33 KB
    __shared__ float zsq_s[PTSB];
    __shared__ float esq_s[CCH];
    __shared__ float warp_s[4];
    __shared__ int   flag_s;
    // red overlays es (only used after all FMAs): 16 x 64 x 8B = 8 KB
    unsigned long long (*red)[PTSB] = (unsigned long long (*)[PTSB])&es[0][0];

    const int tid  = threadIdx.x;
    const int pt_t = tid & 7;     // 0..7  point group (8 pts)
    const int cg   = tid >> 3;    // 0..15 code group (8 codes)
    const int tile = blockIdx.x >> 3;
    const int oct  = blockIdx.x & 7;          // code octant
    const int c0   = oct * CCH;
    const int pt0  = tile * PTSB;
    const int b    = pt0 >> 10;
    const int hw0  = pt0 & 1023;
    const float* zb = z + (size_t)b * BHW + hw0;

    // es transpose: emb chunk [128 codes][64 k] (coalesced float4) -> es[k][c]
    {
        const float4* esrc = (const float4*)(emb + (size_t)c0 * DIM);
        #pragma unroll
        for (int i = 0; i < 16; ++i) {
            int f  = i * 128 + tid;          // float4 index 0..2047
            int c  = f >> 4;                 // 16 float4 per code row
            int k4 = f & 15;
            float4 v = esrc[f];
            es[k4 * 4 + 0][c] = v.x;
            es[k4 * 4 + 1][c] = v.y;
            es[k4 * 4 + 2][c] = v.z;
            es[k4 * 4 + 3][c] = v.w;
        }
    }

    // load z tile (coalesced), natural layout [k][pt]
    #pragma unroll
    for (int i = 0; i < 32; ++i) {
        int f = i * 128 + tid;
        int k = f >> 6, p = f & 63;
        zs[k][p] = zb[(size_t)k * HW + p];
    }

    // one-hot zero-fill: this CTA covers its 1/8 of the tile's 65536 floats
    {
        float* encb = out + OFF_ENC + (size_t)pt0 * NE;
        float4* e4  = (float4*)(encb + 2);
        if (tid == 0) {
            if (oct == 0) { encb[0] = 0.f; encb[1] = 0.f; }
            if (oct == 7) { encb[65534] = 0.f; encb[65535] = 0.f; }
        }
        #pragma unroll
        for (int i = 0; i < 16; ++i) {
            int j = oct * 2048 + i * 128 + tid;
            if (j < 16383) e4[j] = make_float4(0.f, 0.f, 0.f, 0.f);
        }
    }
    __syncthreads();

    // per-point ||z||^2 and per-code ||e||^2, sequential fp32 rn (ref rounding)
    if (tid < PTSB) {
        float s = 0.f;
        #pragma unroll
        for (int k = 0; k < DIM; ++k) {
            float v = zs[k][tid];
            s = __fadd_rn(s, __fmul_rn(v, v));
        }
        zsq_s[tid] = s;
    }
    {
        float s = 0.f;
        #pragma unroll
        for (int k = 0; k < DIM; ++k) {
            float v = es[k][tid];
            s = __fadd_rn(s, __fmul_rn(v, v));
        }
        esq_s[tid] = s;
    }
    __syncthreads();

    unsigned long long best[8];   // MAX-keys; local point lp = pp*2 + (0|1)
    #pragma unroll
    for (int p = 0; p < 8; ++p) best[p] = 0ULL;

    unsigned long long acc[4][8];      // [point-pair][code]
    #pragma unroll
    for (int pp = 0; pp < 4; ++pp)
        #pragma unroll
        for (int j = 0; j < 8; ++j) acc[pp][j] = 0ULL;

    #pragma unroll 8
    for (int k = 0; k < DIM; ++k) {
        // 4 natural point-pairs: points pt_t*4..+3 and 32+pt_t*4..+3
        ull2 zA = *(const ull2*)&zs[k][pt_t * 4];        // pairs 0,1
        ull2 zB = *(const ull2*)&zs[k][32 + pt_t * 4];   // pairs 2,3
        const float* ek = &es[k][cg * 8];
        #pragma unroll
        for (int j = 0; j < 8; ++j) {
            unsigned long long ed = pk2(ek[j]);          // {e,e}
            ffma2(acc[0][j], zA.a, ed);
            ffma2(acc[1][j], zA.b, ed);
            ffma2(acc[2][j], zB.a, ed);
            ffma2(acc[3][j], zB.b, ed);
        }
    }

    // distances + running argmax-key (smaller d and smaller code -> larger key)
    #pragma unroll
    for (int j = 0; j < 8; ++j) {
        float esq = esq_s[cg * 8 + j];
        unsigned codef = (unsigned)(1023 - (c0 + cg * 8 + j));
        #pragma unroll
        for (int pp = 0; pp < 4; ++pp) {
            int pbase = (pp >> 1) * 32 + pt_t * 4 + (pp & 1) * 2;
            float2 dot = upk(acc[pp][j]);
            {
                float zq2 = zsq_s[pbase];
                float d = __fadd_rn(__fadd_rn(zq2, esq), -2.0f * dot.x);
                unsigned long long k64 =
                    ((unsigned long long)(ordf(d) ^ 0xFFFFFFFFu) << 32) | codef;
                if (k64 > best[pp * 2]) best[pp * 2] = k64;
            }
            {
                float zq2 = zsq_s[pbase + 1];
                float d = __fadd_rn(__fadd_rn(zq2, esq), -2.0f * dot.y);
                unsigned long long k64 =
                    ((unsigned long long)(ordf(d) ^ 0xFFFFFFFFu) << 32) | codef;
                if (k64 > best[pp * 2 + 1]) best[pp * 2 + 1] = k64;
            }
        }
    }

    // cross-thread argmin reduction within CTA (red overlays es)
    __syncthreads();
    #pragma unroll
    for (int pp = 0; pp < 4; ++pp) {
        int pbase = (pp >> 1) * 32 + pt_t * 4 + (pp & 1) * 2;
        red[cg][pbase]     = best[pp * 2];
        red[cg][pbase + 1] = best[pp * 2 + 1];
    }
    __syncthreads();

    if (tid < PTSB) {
        unsigned long long bk = red[0][tid];
        #pragma unroll
        for (int t = 1; t < 16; ++t) {
            unsigned long long v = red[t][tid];
            if (v > bk) bk = v;
        }
        atomicMax(&d_best[pt0 + tid], bk);
    }

    // tile ticket: 8th arriving CTA runs the epilogue
    __threadfence();
    __syncthreads();
    if (tid == 0) flag_s = (atomicAdd(&d_tile[tile], 1u) == NSPLIT - 1) ? 1 : 0;
    __syncthreads();
    if (!flag_s) return;

    if (tid < PTSB) {
        int n = pt0 + tid;
        unsigned long long bk =
            *((volatile unsigned long long*)&d_best[n]);   // final (all fenced)
        d_best[n] = 0ULL;                                  // reset for replay
        int idx = 1023 - (int)(unsigned int)(bk & 0xFFFFFFFFu);

        out[OFF_IDX + n] = (float)idx;
        atomicAdd(&d_count[idx], 1u);
        out[OFF_ENC + (unsigned long long)n * NE + (unsigned)idx] = 1.0f;

        // z_q gather + loss partial (straight-through: z_q_out == z_q in value)
        float errsum = 0.f;
        const float* er = emb + (size_t)idx * DIM;
        float* zq = out + OFF_ZQ + (size_t)b * BHW + hw0 + tid;
        #pragma unroll
        for (int c = 0; c < DIM; ++c) {
            float e  = __ldg(er + c);
            float zv = zs[c][tid];
            float df = e - zv;
            errsum   = fmaf(df, df, errsum);
            zq[(size_t)c * HW] = e;
        }
        #pragma unroll
        for (int o = 16; o > 0; o >>= 1)
            errsum += __shfl_down_sync(0xFFFFFFFFu, errsum, o);
        if ((tid & 31) == 0) atomicAdd(&d_loss, errsum);
    }
    if (tid == 0) d_tile[tile] = 0u;                       // reset for replay

    // global ticket: last epilogue CTA computes perplexity + loss scalars
    __threadfence();
    __syncthreads();
    if (tid == 0) flag_s = (atomicAdd(&d_done, 1u) == NTILE - 1) ? 1 : 0;
    __syncthreads();
    if (flag_s) {
        float part = 0.f;
        #pragma unroll
        for (int i = 0; i < 8; ++i) {
            int c = tid + i * 128;
            unsigned cnt = *((volatile unsigned int*)&d_count[c]);
            d_count[c] = 0u;                               // reset for replay
            float em = (float)cnt * (1.0f / 32768.0f);
            part += em * logf(em + 1e-10f);
        }
        #pragma unroll
        for (int o = 16; o > 0; o >>= 1)
            part += __shfl_down_sync(0xFFFFFFFFu, part, o);
        if ((tid & 31) == 0) warp_s[tid >> 5] = part;
        __syncthreads();
        if (tid == 0) {
            float w = warp_s[0] + warp_s[1] + warp_s[2] + warp_s[3];
            out[OFF_PERP] = expf(-w);
            out[OFF_LOSS] = 1.25f * (*((volatile float*)&d_loss))
                            * (1.0f / 2097152.0f);
            d_loss = 0.f;                                  // reset for replay
            d_done = 0u;
        }
    }
}

// ---------------------------------------------------------------- launch
extern "C" void kernel_launch(void* const* d_in, const int* in_sizes, int n_in,
                              void* d_out, int out_size) {
    const float* z   = (const float*)d_in[0];
    const float* emb = (const float*)d_in[1];
    float*       out = (float*)d_out;

    vq_main_kernel<<<NBLK, 128>>>(z, emb, out);
}

// round 17
// speedup vs baseline: 1.0566x; 1.0566x over previous
#include <cuda_runtime.h>
#include <cstdint>

// Problem constants
#define NPTS   32768            // 32 * 32 * 32 points
#define DIM    64               // embedding dim
#define NE     1024             // codebook size
#define HW     1024             // 32*32 spatial
#define BHW    65536            // 64 channels * 1024 hw (per-batch stride in z)
#define PTSB   64               // points per tile
#define CCH    128              // codes per CTA (one chunk, no refill)
#define NTILE  (NPTS / PTSB)    // 512 point tiles
#define NSPLIT 8                // code-split CTAs per tile
#define NBLK   (NTILE * NSPLIT) // 4096 CTAs

// Output layout (flat concat of reference return tuple, float32):
// loss[1], z_q[2097152], perplexity[1], min_encodings[33554432], indices[32768]
#define OFF_LOSS 0ULL
#define OFF_ZQ   1ULL
#define OFF_PERP 2097153ULL
#define OFF_ENC  2097154ULL
#define OFF_IDX  35651586ULL

__device__ float              d_esq[NE];
__device__ float              d_est[DIM * NE];   // transposed codebook [k][c]
__device__ float              d_zsq[NPTS];       // precomputed ||z||^2
__device__ unsigned int       d_count[NE];
__device__ unsigned long long d_best[NPTS];      // argmin keys (atomicMin merge)
__device__ unsigned int       d_tile[NTILE];     // per-tile arrival tickets
__device__ float              d_loss;
__device__ unsigned int       d_done;

// ---------------------------------------------------------------- helpers
struct __align__(16) ull2 { unsigned long long a, b; };

static __device__ __forceinline__ unsigned long long pk2(float v) {
    unsigned long long r;
    asm("mov.b64 %0, {%1,%2};" : "=l"(r) : "f"(v), "f"(v));
    return r;
}
static __device__ __forceinline__ void ffma2(unsigned long long& d,
                                             unsigned long long a,
                                             unsigned long long b) {
    asm("fma.rn.f32x2 %0, %1, %2, %0;" : "+l"(d) : "l"(a), "l"(b));
}
static __device__ __forceinline__ float2 upk(unsigned long long v) {
    float2 f;
    asm("mov.b64 {%0,%1}, %2;" : "=f"(f.x), "=f"(f.y) : "l"(v));
    return f;
}
static __device__ __forceinline__ unsigned int ordf(float x) {
    unsigned int b = __float_as_uint(x);
    return b ^ (unsigned int)(((int)b >> 31) | 0x80000000);
}
static __device__ __forceinline__ void cpasync16(unsigned int dst_smem,
                                                 const void* src) {
    asm volatile("cp.async.ca.shared.global [%0], [%1], 16;"
                 :: "r"(dst_smem), "l"(src));
}
#define CP_COMMIT() asm volatile("cp.async.commit_group;" ::: "memory")
#define CP_WAIT0()  asm volatile("cp.async.wait_group 0;" ::: "memory")

// ---------------------------------------------------------------- prep (fused with zsq)
// 256 blocks x 128 threads.
// ALL blocks: per-point ||z||^2 for their 128 points + reset merge state.
// Blocks 0-15: codebook transpose + ||e||^2 + counter reset.
__global__ void prep_kernel(const float* __restrict__ z,
                            const float* __restrict__ emb) {
    __shared__ float sb[64][DIM + 1];
    const int tid = threadIdx.x;
    const int bid = blockIdx.x;
    const int g   = bid * 128 + tid;           // 0..32767

    // zsq: sequential fp32 rn (identical rounding order to reference match)
    {
        const int b  = g >> 10;
        const int hw = g & 1023;
        const float* p = z + (size_t)b * BHW + hw;
        float s = 0.f;
        #pragma unroll
        for (int k = 0; k < DIM; ++k) {
            float v = p[(size_t)k * HW];
            s = __fadd_rn(s, __fmul_rn(v, v));
        }
        d_zsq[g] = s;
    }

    // reset merge state every launch
    d_best[g] = 0xFFFFFFFFFFFFFFFFULL;
    if (g < NTILE) d_tile[g] = 0u;
    if (g == 0) { d_loss = 0.f; d_done = 0u; }

    if (bid < 16) {
        const int c0 = bid * 64;
        const float4* src = (const float4*)(emb + (size_t)c0 * DIM);
        #pragma unroll
        for (int i = 0; i < 8; ++i) {
            int f  = i * 128 + tid;
            int c  = f >> 4;
            int k4 = f & 15;
            float4 v = src[f];
            sb[c][k4 * 4 + 0] = v.x;
            sb[c][k4 * 4 + 1] = v.y;
            sb[c][k4 * 4 + 2] = v.z;
            sb[c][k4 * 4 + 3] = v.w;
        }
        __syncthreads();

        if (tid < 64) {
            const int c = c0 + tid;
            float s = 0.f;
            #pragma unroll
            for (int k = 0; k < DIM; ++k) {
                float v = sb[tid][k];
                s = __fadd_rn(s, __fmul_rn(v, v));
                d_est[k * NE + c] = v;
            }
            d_esq[c]   = s;
            d_count[c] = 0u;
        }
    }
}

// ---------------------------------------------------------------- main fused kernel
// Exact R15 kernel (best measured). CTA = (tile, octant): 64 pts x 128 codes.
// 128 threads = 8 pt-groups (pt_t, 8 pts) x 16 code-groups (cg, 8 codes)
// thread tile: 8 points (4 NATURAL f32x2 pairs) x 8 codes (pk2-dup es).
__global__ void __launch_bounds__(128, 4)
vq_main_kernel(const float* __restrict__ z, const float* __restrict__ emb,
               float* __restrict__ out)
{
    __shared__ __align__(16) float zs[DIM][PTSB];      // [k][pt] 16 KB
    __shared__ __align__(16) float es[DIM][CCH];       // [k][c] 32 KB
    __shared__ float zsq_s[PTSB];
    __shared__ float warp_s[4];
    __shared__ int   flag_s;
    // red overlays es (only used after all FMAs): 16 x 64 x 8B = 8 KB
    unsigned long long (*red)[PTSB] = (unsigned long long (*)[PTSB])&es[0][0];

    const int tid  = threadIdx.x;
    const int pt_t = tid & 7;     // 0..7  point group (8 pts)
    const int cg   = tid >> 3;    // 0..15 code group (8 codes)
    const int tile = blockIdx.x >> 3;
    const int oct  = blockIdx.x & 7;          // code octant
    const int c0   = oct * CCH;
    const int pt0  = tile * PTSB;
    const int b    = pt0 >> 10;
    const int hw0  = pt0 & 1023;
    const float* zb = z + (size_t)b * BHW + hw0;

    // issue the single es chunk fetch immediately (32 KB from d_est)
    {
        unsigned int dst0 = (unsigned int)__cvta_generic_to_shared(&es[0][0]);
        #pragma unroll
        for (int i = 0; i < 16; ++i) {
            int f = i * 128 + tid;           // 16B unit 0..2047
            int k = f >> 5, c16 = f & 31;    // 32 units per k-row
            cpasync16(dst0 + (unsigned)(k * CCH + c16 * 4) * 4u,
                      &d_est[(size_t)k * NE + c0 + c16 * 4]);
        }
        CP_COMMIT();
    }

    // load z tile (coalesced), natural layout [k][pt]
    #pragma unroll
    for (int i = 0; i < 32; ++i) {
        int f = i * 128 + tid;
        int k = f >> 6, p = f & 63;
        zs[k][p] = zb[(size_t)k * HW + p];
    }

    // precomputed ||z||^2
    if (tid < PTSB) zsq_s[tid] = d_zsq[pt0 + tid];

    // one-hot zero-fill: this CTA covers its 1/8 of the tile's 65536 floats
    {
        float* encb = out + OFF_ENC + (size_t)pt0 * NE;
        float4* e4  = (float4*)(encb + 2);
        if (tid == 0) {
            if (oct == 0) { encb[0] = 0.f; encb[1] = 0.f; }
            if (oct == 7) { encb[65534] = 0.f; encb[65535] = 0.f; }
        }
        #pragma unroll
        for (int i = 0; i < 16; ++i) {
            int j = oct * 2048 + i * 128 + tid;
            if (j < 16383) e4[j] = make_float4(0.f, 0.f, 0.f, 0.f);
        }
    }

    CP_WAIT0();
    __syncthreads();           // es + zs + zsq_s visible

    unsigned long long best[8];   // local point lp = pp*2 + (0|1)
    #pragma unroll
    for (int p = 0; p < 8; ++p) best[p] = 0xFFFFFFFFFFFFFFFFULL;

    unsigned long long acc[4][8];      // [point-pair][code]
    #pragma unroll
    for (int pp = 0; pp < 4; ++pp)
        #pragma unroll
        for (int j = 0; j < 8; ++j) acc[pp][j] = 0ULL;

    #pragma unroll 8
    for (int k = 0; k < DIM; ++k) {
        // 4 natural point-pairs: points pt_t*4..+3 and 32+pt_t*4..+3
        ull2 zA = *(const ull2*)&zs[k][pt_t * 4];        // pairs 0,1
        ull2 zB = *(const ull2*)&zs[k][32 + pt_t * 4];   // pairs 2,3
        const float* ek = &es[k][cg * 8];
        #pragma unroll
        for (int j = 0; j < 8; ++j) {
            unsigned long long ed = pk2(ek[j]);          // {e,e}
            ffma2(acc[0][j], zA.a, ed);
            ffma2(acc[1][j], zA.b, ed);
            ffma2(acc[2][j], zB.a, ed);
            ffma2(acc[3][j], zB.b, ed);
        }
    }

    // distances + running argmin (u64 key -> first-index tie-break)
    const int cbase = c0 + cg * 8;
    #pragma unroll
    for (int j = 0; j < 8; ++j) {
        float esq = __ldg(&d_esq[cbase + j]);
        unsigned code = (unsigned)(cbase + j);
        #pragma unroll
        for (int pp = 0; pp < 4; ++pp) {
            int pbase = (pp >> 1) * 32 + pt_t * 4 + (pp & 1) * 2;
            float2 dot = upk(acc[pp][j]);
            {
                float zq2 = zsq_s[pbase];
                float d = __fadd_rn(__fadd_rn(zq2, esq), -2.0f * dot.x);
                unsigned long long k64 =
                    ((unsigned long long)ordf(d) << 32) | code;
                if (k64 < best[pp * 2]) best[pp * 2] = k64;
            }
            {
                float zq2 = zsq_s[pbase + 1];
                float d = __fadd_rn(__fadd_rn(zq2, esq), -2.0f * dot.y);
                unsigned long long k64 =
                    ((unsigned long long)ordf(d) << 32) | code;
                if (k64 < best[pp * 2 + 1]) best[pp * 2 + 1] = k64;
            }
        }
    }

    // cross-thread argmin reduction within CTA (red overlays es)
    __syncthreads();
    #pragma unroll
    for (int pp = 0; pp < 4; ++pp) {
        int pbase = (pp >> 1) * 32 + pt_t * 4 + (pp & 1) * 2;
        red[cg][pbase]     = best[pp * 2];
        red[cg][pbase + 1] = best[pp * 2 + 1];
    }
    __syncthreads();

    if (tid < PTSB) {
        unsigned long long bk = red[0][tid];
        #pragma unroll
        for (int t = 1; t < 16; ++t) {
            unsigned long long v = red[t][tid];
            if (v < bk) bk = v;
        }
        atomicMin(&d_best[pt0 + tid], bk);
    }

    // tile ticket: 8th arriving CTA runs the epilogue
    __threadfence();
    __syncthreads();
    if (tid == 0) flag_s = (atomicAdd(&d_tile[tile], 1u) == NSPLIT - 1) ? 1 : 0;
    __syncthreads();
    if (!flag_s) return;

    if (tid < PTSB) {
        int n   = pt0 + tid;
        unsigned long long bk =
            *((volatile unsigned long long*)&d_best[n]);   // final (all fenced)
        int idx = (int)(unsigned int)bk;

        out[OFF_IDX + n] = (float)idx;
        atomicAdd(&d_count[idx], 1u);
        out[OFF_ENC + (unsigned long long)n * NE + (unsigned)idx] = 1.0f;

        // z_q gather + loss partial (straight-through: z_q_out == z_q in value)
        float errsum = 0.f;
        const float* er = emb + (size_t)idx * DIM;
        float* zq = out + OFF_ZQ + (size_t)b * BHW + hw0 + tid;
        #pragma unroll
        for (int c = 0; c < DIM; ++c) {
            float e  = __ldg(er + c);
            float zv = zs[c][tid];
            float df = e - zv;
            errsum   = fmaf(df, df, errsum);
            zq[(size_t)c * HW] = e;
        }
        #pragma unroll
        for (int o = 16; o > 0; o >>= 1)
            errsum += __shfl_down_sync(0xFFFFFFFFu, errsum, o);
        if ((tid & 31) == 0) atomicAdd(&d_loss, errsum);
    }

    // global ticket: last epilogue CTA computes perplexity + loss scalars
    __threadfence();
    __syncthreads();
    if (tid == 0) flag_s = (atomicAdd(&d_done, 1u) == NTILE - 1) ? 1 : 0;
    __syncthreads();
    if (flag_s) {
        float part = 0.f;
        #pragma unroll
        for (int i = 0; i < 8; ++i) {
            int c = tid + i * 128;
            float em = (float)*((volatile unsigned int*)&d_count[c])
                       * (1.0f / 32768.0f);
            part += em * logf(em + 1e-10f);
        }
        #pragma unroll
        for (int o = 16; o > 0; o >>= 1)
            part += __shfl_down_sync(0xFFFFFFFFu, part, o);
        if ((tid & 31) == 0) warp_s[tid >> 5] = part;
        __syncthreads();
        if (tid == 0) {
            float w = warp_s[0] + warp_s[1] + warp_s[2] + warp_s[3];
            out[OFF_PERP] = expf(-w);
            out[OFF_LOSS] = 1.25f * (*((volatile float*)&d_loss))
                            * (1.0f / 2097152.0f);
        }
    }
}

// ---------------------------------------------------------------- launch
extern "C" void kernel_launch(void* const* d_in, const int* in_sizes, int n_in,
                              void* d_out, int out_size) {
    const float* z   = (const float*)d_in[0];
    const float* emb = (const float*)d_in[1];
    float*       out = (float*)d_out;

    prep_kernel<<<NPTS / 128, 128>>>(z, emb);
    vq_main_kernel<<<NBLK, 128>>>(z, emb, out);
}